// round 6
// baseline (speedup 1.0000x reference)
#include <cuda_runtime.h>

// MaxPool2d: kernel=2, stride=2, padding=0
// Input:  (32, 64, 224, 224) fp32  -> NC = 2048 planes of 224x224
// Output: (32, 64, 112, 112) fp32
//
// R5: persistent one-wave grid-stride version of R4.
//     1184 CTAs (148 SMs x 8 resident CTAs @ 256 thr, regs ~26).
//     Each thread loops over ~21 float4-output-groups with stride =
//     total threads, preserving exact R4 per-instruction coalescing
//     (lanes -> consecutive 16B) while amortizing prologue and
//     eliminating ~20 wave transitions.

#define IN_H    224
#define IN_W    224
#define OUT_H   112
#define OUT_W   112
#define NC      (32 * 64)

#define OW4     (OUT_W / 4)                 // 28 float4 groups per output row
#define TOTAL   (NC * OUT_H * OW4)          // 6,422,528 groups

#define GRID    1184                        // 148 SMs * 8 CTAs
#define BLOCK   256
#define NTHREADS (GRID * BLOCK)             // 303,104

__global__ __launch_bounds__(BLOCK)
void maxpool2d_k2s2_kernel(const float* __restrict__ in,
                           float* __restrict__ out)
{
    unsigned g = blockIdx.x * (unsigned)BLOCK + threadIdx.x;

    #pragma unroll 2
    for (; g < (unsigned)TOTAL; g += (unsigned)NTHREADS) {
        // 32-bit div/mod by constants -> magic-multiply IMADs
        const unsigned ow4 = g % OW4;
        const unsigned tmp = g / OW4;
        const unsigned oh  = tmp % OUT_H;
        const unsigned nc  = tmp / OUT_H;

        const float* row0 = in + (size_t)nc * (IN_H * IN_W)
                               + (size_t)(2u * oh) * IN_W
                               + ow4 * 8u;
        const float* row1 = row0 + IN_W;

        // 4 independent 128-bit loads (MLP=4 per iter, overlapped across iters)
        const float4 a0 = *reinterpret_cast<const float4*>(row0);
        const float4 a1 = *reinterpret_cast<const float4*>(row0 + 4);
        const float4 b0 = *reinterpret_cast<const float4*>(row1);
        const float4 b1 = *reinterpret_cast<const float4*>(row1 + 4);

        float4 o;
        o.x = fmaxf(fmaxf(a0.x, a0.y), fmaxf(b0.x, b0.y));
        o.y = fmaxf(fmaxf(a0.z, a0.w), fmaxf(b0.z, b0.w));
        o.z = fmaxf(fmaxf(a1.x, a1.y), fmaxf(b1.x, b1.y));
        o.w = fmaxf(fmaxf(a1.z, a1.w), fmaxf(b1.z, b1.w));

        float* outp = out + (size_t)nc * (OUT_H * OUT_W)
                          + (size_t)oh * OUT_W
                          + ow4 * 4u;
        *reinterpret_cast<float4*>(outp) = o;
    }
}

extern "C" void kernel_launch(void* const* d_in, const int* in_sizes, int n_in,
                              void* d_out, int out_size)
{
    const float* x = (const float*)d_in[0];
    float* y = (float*)d_out;

    maxpool2d_k2s2_kernel<<<GRID, BLOCK>>>(x, y);
}

// round 7
// speedup vs baseline: 1.0649x; 1.0649x over previous
#include <cuda_runtime.h>

// MaxPool2d: kernel=2, stride=2, padding=0
// Input:  (32, 64, 224, 224) fp32  -> NC = 2048 planes of 224x224
// Output: (32, 64, 112, 112) fp32
//
// R6: fully-coalesced-per-instruction layout.
//     Unit = (plane, output row, float4 column chunk): thread loads
//     in[2oh][4c4..4c4+4) and in[2oh+1][...] -- lanes hit CONSECUTIVE
//     16B (4 lines per LDG.128, minimal L1tex wavefronts), computes
//     vertical max then horizontal pair max -> float2 output (coalesced
//     8B stores). 2 warp-strided units per thread -> MLP=4.
//     12,845,056 units == 25088 blocks * 512. No tail.

#define IN_H    224
#define IN_W    224
#define OUT_H   112
#define OUT_W   112
#define NC      (32 * 64)

#define C4      (IN_W / 4)                  // 56 float4 chunks per input row
#define TOTAL   (NC * OUT_H * C4)           // 12,845,056 == 25088 * 512

__device__ __forceinline__ void unit(unsigned g,
                                     const float* __restrict__ in,
                                     float* __restrict__ out)
{
    // 32-bit div/mod by constants -> magic-multiply IMADs
    const unsigned c4  = g % C4;
    const unsigned tmp = g / C4;
    const unsigned oh  = tmp % OUT_H;
    const unsigned nc  = tmp / OUT_H;

    const float* p = in + (size_t)nc * (IN_H * IN_W)
                        + (size_t)(2u * oh) * IN_W
                        + c4 * 4u;

    // Two fully-coalesced LDG.128 (lanes -> consecutive 16B)
    const float4 a = *reinterpret_cast<const float4*>(p);
    const float4 b = *reinterpret_cast<const float4*>(p + IN_W);

    // vertical max, then horizontal pair max -> 2 outputs
    float2 o;
    o.x = fmaxf(fmaxf(a.x, b.x), fmaxf(a.y, b.y));
    o.y = fmaxf(fmaxf(a.z, b.z), fmaxf(a.w, b.w));

    float* q = out + (size_t)nc * (OUT_H * OUT_W)
                   + (size_t)oh * OUT_W
                   + c4 * 2u;
    *reinterpret_cast<float2*>(q) = o;
}

__global__ __launch_bounds__(256)
void maxpool2d_k2s2_kernel(const float* __restrict__ in,
                           float* __restrict__ out)
{
    const unsigned base = blockIdx.x * 512u + threadIdx.x;
    // two warp-strided units -> 4 front-batched loads (MLP=4)
    unit(base,        in, out);
    unit(base + 256u, in, out);
}

extern "C" void kernel_launch(void* const* d_in, const int* in_sizes, int n_in,
                              void* d_out, int out_size)
{
    const float* x = (const float*)d_in[0];
    float* y = (float*)d_out;

    maxpool2d_k2s2_kernel<<<TOTAL / 512, 256>>>(x, y);   // 25088 blocks, exact
}